// round 3
// baseline (speedup 1.0000x reference)
#include <cuda_runtime.h>

// ---------------------------------------------------------------------------
// HGT layer: per-ntype kqv projection -> 8-etype edge attention (segment
// softmax, max-shift skipped: values are O(1)) -> per-node relation bmm +
// mean cross-reduce + relu + LayerNorm.
//
// Pipeline:
//   K0 zero scratch (den, w accumulators)
//   K1 projection GEMM (f32x2 packed FMA)
//   K2 edge pass: att -> exp -> red.v4 accumulate (ex*v) and den per dst
//   K3 node pass: (w/den) @ msg[e], sum over etypes, relu+LN, write out
// ---------------------------------------------------------------------------

#define E_PER  150000
#define NNODE  22050
#define WTOT   64150   // sum over etypes of dst-ntype node counts

__device__ float g_k[NNODE * 128];
__device__ float g_q[NNODE * 128];
__device__ float g_v[NNODE * 128];
__device__ float g_w[(size_t)WTOT * 128];   // per-(etype,dst) sum ex*v
__device__ float g_den[(size_t)WTOT * 8];   // per-(etype,dst,head) sum ex

__constant__ int   c_off[3]    = {0, 20000, 20050};
__constant__ int   c_nt[3]     = {20000, 50, 2000};
__constant__ int   c_src_t[8]  = {0, 0, 1, 1, 0, 1, 2, 2};
__constant__ int   c_dst_t[8]  = {1, 2, 2, 1, 0, 0, 1, 0};
__constant__ int   c_woff[8]   = {0, 50, 2050, 4050, 4100, 24100, 44100, 44150};
__constant__ int   c_t2e[3][3] = {{4, 5, 7}, {0, 3, 6}, {1, 2, -1}};
__constant__ float c_invcnt[3] = {1.0f / 3.0f, 1.0f / 3.0f, 0.5f};

// ---------------------------------------------------------------------------
// K0: zero the accumulators (must re-zero every launch: graph replays)
// ---------------------------------------------------------------------------
__global__ void zero_kernel()
{
    int i = blockIdx.x * 256 + threadIdx.x;
    int stride = gridDim.x * 256;
    float4 z = {0.f, 0.f, 0.f, 0.f};
    float4* w4 = reinterpret_cast<float4*>(g_w);
    float4* d4 = reinterpret_cast<float4*>(g_den);
    for (int k = i; k < WTOT * 32; k += stride) w4[k] = z;
    for (int k = i; k < WTOT * 2;  k += stride) d4[k] = z;
}

// ---------------------------------------------------------------------------
// K1: projections. block = 128 threads (one per out col), 32 nodes per block.
// blockIdx.y in {k,q,v}, blockIdx.z = ntype. Packed f32x2 FMA: 2 nodes/instr.
// ---------------------------------------------------------------------------
__global__ void __launch_bounds__(128) proj_kernel(
    const float* __restrict__ xw, const float* __restrict__ xt,
    const float* __restrict__ xd,
    const float* __restrict__ Wk, const float* __restrict__ bk,
    const float* __restrict__ Wq, const float* __restrict__ bq,
    const float* __restrict__ Wv, const float* __restrict__ bv)
{
    int t  = blockIdx.z;
    int Nt = c_nt[t];
    int n0 = blockIdx.x * 32;
    if (n0 >= Nt) return;

    const float* x = (t == 0) ? xw : (t == 1) ? xt : xd;
    int m = blockIdx.y;
    const float* W = ((m == 0) ? Wk : (m == 1) ? Wq : Wv) + t * 256 * 128;
    const float* b = ((m == 0) ? bk : (m == 1) ? bq : bv) + t * 128;
    float* out = ((m == 0) ? g_k : (m == 1) ? g_q : g_v) + (size_t)(c_off[t] + n0) * 128;

    int j = threadIdx.x;  // output column 0..127

    unsigned long long acc2[16];  // node pairs (2p, 2p+1), packed f32x2
#pragma unroll
    for (int p = 0; p < 16; p++) acc2[p] = 0ull;

    __shared__ float xs[16][32];  // [k-chunk][node]

    for (int kk = 0; kk < 256; kk += 16) {
        __syncthreads();
#pragma unroll
        for (int p = 0; p < 4; p++) {
            int idx = j + p * 128;
            int kc = idx >> 5, i = idx & 31;
            int n = n0 + i;
            xs[kc][i] = (n < Nt) ? x[(size_t)n * 256 + kk + kc] : 0.0f;
        }
        __syncthreads();
#pragma unroll
        for (int kc = 0; kc < 16; kc++) {
            float wv = W[(size_t)(kk + kc) * 128 + j];
            unsigned long long w2;
            asm("mov.b64 %0, {%1,%1};" : "=l"(w2) : "f"(wv));
#pragma unroll
            for (int p = 0; p < 16; p++) {
                unsigned long long xv =
                    *reinterpret_cast<const unsigned long long*>(&xs[kc][2 * p]);
                asm("fma.rn.f32x2 %0, %1, %2, %3;"
                    : "=l"(acc2[p]) : "l"(xv), "l"(w2), "l"(acc2[p]));
            }
        }
    }

    float bb = b[j];
#pragma unroll
    for (int p = 0; p < 16; p++) {
        float lo, hi;
        asm("mov.b64 {%0,%1}, %2;" : "=f"(lo), "=f"(hi) : "l"(acc2[p]));
        int n = n0 + 2 * p;
        if (n < Nt)     out[(size_t)(2 * p) * 128 + j]     = lo + bb;
        if (n + 1 < Nt) out[(size_t)(2 * p + 1) * 128 + j] = hi + bb;
    }
}

// ---------------------------------------------------------------------------
// K2: one warp per edge. lane l handles dims [4l, 4l+4) (head h = l>>2).
// att = (q_d . k_s)_h * pri[e,h] / 4 ; ex = exp(att) (no max shift needed)
// accumulate ex into den[d,h] and ex*v into w[d,:] via vector red.
// ---------------------------------------------------------------------------
__global__ void __launch_bounds__(256) edge_kernel(
    const int* __restrict__ esrc, const int* __restrict__ edst,
    const float* __restrict__ pri)
{
    int gw = blockIdx.x * 8 + (threadIdx.x >> 5);  // global warp = edge id
    int l  = threadIdx.x & 31;
    int e  = gw / E_PER;
    int i  = gw - e * E_PER;

    int s = esrc[e * E_PER + i];
    int d = edst[e * E_PER + i];
    int sg = c_off[c_src_t[e]] + s;
    int dg = c_off[c_dst_t[e]] + d;

    float4 qv = *reinterpret_cast<const float4*>(g_q + (size_t)dg * 128 + 4 * l);
    float4 kv = *reinterpret_cast<const float4*>(g_k + (size_t)sg * 128 + 4 * l);
    float4 vv = *reinterpret_cast<const float4*>(g_v + (size_t)sg * 128 + 4 * l);

    float p = qv.x * kv.x + qv.y * kv.y + qv.z * kv.z + qv.w * kv.w;
    p += __shfl_xor_sync(0xffffffffu, p, 1);
    p += __shfl_xor_sync(0xffffffffu, p, 2);   // head-group (4 lanes) sum

    int h = l >> 2;
    float ex = __expf(p * pri[e * 8 + h] * 0.25f);

    if ((l & 3) == 0)
        atomicAdd(&g_den[((size_t)c_woff[e] + d) * 8 + h], ex);

    float* wp = &g_w[((size_t)c_woff[e] + d) * 128 + 4 * l];
    asm volatile("red.global.add.v4.f32 [%0], {%1,%2,%3,%4};"
                 :: "l"(wp), "f"(ex * vv.x), "f"(ex * vv.y),
                    "f"(ex * vv.z), "f"(ex * vv.w)
                 : "memory");
}

// ---------------------------------------------------------------------------
// K3: one warp per output node. lane l owns output cols [4l, 4l+4)
// (head h = l>>2, in-head offset f0 = (l&3)*4).
// te = (w/den) @ msg[e,h]  summed over delivering etypes, then
// relu(mean cross-reduce) + LayerNorm.
// ---------------------------------------------------------------------------
__global__ void __launch_bounds__(256) out_kernel(
    const float* __restrict__ msg, const float* __restrict__ gamma,
    const float* __restrict__ beta, float* __restrict__ out)
{
    int n = blockIdx.x * 8 + (threadIdx.x >> 5);
    if (n >= NNODE) return;
    int l = threadIdx.x & 31;
    int t = (n < 20000) ? 0 : (n < 20050) ? 1 : 2;
    int local = n - c_off[t];
    int h  = l >> 2;
    int f0 = (l & 3) * 4;

    float acc[4] = {0.f, 0.f, 0.f, 0.f};
#pragma unroll
    for (int ee = 0; ee < 3; ee++) {
        int e = c_t2e[t][ee];
        if (e < 0) continue;
        float den = g_den[((size_t)c_woff[e] + local) * 8 + h];
        if (den > 0.f) {
            float inv = 1.0f / den;
            const float* wrow = &g_w[((size_t)c_woff[e] + local) * 128 + h * 16];
            const float* mbase = msg + (size_t)((e * 8 + h) * 16) * 16 + f0;
#pragma unroll
            for (int dd = 0; dd < 16; dd++) {
                float wd = wrow[dd] * inv;
                const float* mr = mbase + dd * 16;
                acc[0] += wd * mr[0];
                acc[1] += wd * mr[1];
                acc[2] += wd * mr[2];
                acc[3] += wd * mr[3];
            }
        }
    }

    float ic = c_invcnt[t];
    float hv[4], s = 0.f, s2 = 0.f;
#pragma unroll
    for (int j = 0; j < 4; j++) {
        float v = fmaxf(acc[j] * ic, 0.f);
        hv[j] = v;
        s += v;
        s2 += v * v;
    }
#pragma unroll
    for (int o = 16; o >= 1; o >>= 1) {
        s  += __shfl_xor_sync(0xffffffffu, s,  o);
        s2 += __shfl_xor_sync(0xffffffffu, s2, o);
    }
    float mu   = s * (1.0f / 128.0f);
    float var  = s2 * (1.0f / 128.0f) - mu * mu;
    float rstd = rsqrtf(var + 1e-5f);
#pragma unroll
    for (int j = 0; j < 4; j++) {
        int col = 4 * l + j;
        out[(size_t)n * 128 + col] =
            (hv[j] - mu) * rstd * gamma[t * 128 + col] + beta[t * 128 + col];
    }
}

// ---------------------------------------------------------------------------
extern "C" void kernel_launch(void* const* d_in, const int* in_sizes, int n_in,
                              void* d_out, int out_size)
{
    const float* xw    = (const float*)d_in[0];
    const float* xt    = (const float*)d_in[1];
    const float* xd    = (const float*)d_in[2];
    const float* Wk    = (const float*)d_in[3];
    const float* bk    = (const float*)d_in[4];
    const float* Wq    = (const float*)d_in[5];
    const float* bq    = (const float*)d_in[6];
    const float* Wv    = (const float*)d_in[7];
    const float* bv    = (const float*)d_in[8];
    const float* pri   = (const float*)d_in[9];
    const float* msg   = (const float*)d_in[10];
    const float* gamma = (const float*)d_in[11];
    const float* beta  = (const float*)d_in[12];
    const int*   esrc  = (const int*)d_in[13];
    const int*   edst  = (const int*)d_in[14];
    float* out = (float*)d_out;

    zero_kernel<<<2048, 256>>>();
    dim3 gp(625, 3, 3);
    proj_kernel<<<gp, 128>>>(xw, xt, xd, Wk, bk, Wq, bq, Wv, bv);
    edge_kernel<<<E_PER, 256>>>(esrc, edst, pri);
    out_kernel<<<(NNODE + 7) / 8, 256>>>(msg, gamma, beta, out);
}

// round 5
// speedup vs baseline: 1.0403x; 1.0403x over previous
#include <cuda_runtime.h>

// ---------------------------------------------------------------------------
// HGT layer, round 4: counting-sort edge phase + vectorized node epilogue.
//
//   K0 zero   : g_w, g_den, g_cnt; transpose msg -> g_msgT [e][dd][h][f]
//   K1 hist   : per-edge histogram over (etype,dst) slots
//   K2 scan   : exclusive prefix sum over 64150 slot counters (1 block)
//   K3 scatter: sorted edge records rec = (slot<<15)|src_global (u32)
//   K4 proj   : kqv projection GEMM (f32x2 packed FMA)  [unchanged]
//   K5 accum  : warp per 64-edge chunk of sorted stream; register
//               accumulation per run; red.v4 flush per run (not per edge)
//   K6 out    : coalesced w-row float4 + shfl + transposed msg float4,
//               relu + mean cross-reduce + LayerNorm
// ---------------------------------------------------------------------------

#define E_PER  150000
#define E_TOT  1200000
#define NNODE  22050
#define WTOT   64150
#define CH     64
#define NCHUNK (E_TOT / CH)   // 18750

__device__ float    g_k[NNODE * 128];
__device__ float    g_q[NNODE * 128];
__device__ float    g_v[NNODE * 128];
__device__ float    g_w[(size_t)WTOT * 128];
__device__ float    g_den[(size_t)WTOT * 8];
__device__ int      g_cnt[WTOT];
__device__ int      g_pos[WTOT];
__device__ unsigned g_rec[E_TOT];
__device__ float    g_msgT[8 * 16 * 8 * 16];   // [e][dd][h][f]

__constant__ int   c_off[3]    = {0, 20000, 20050};
__constant__ int   c_nt[3]     = {20000, 50, 2000};
__constant__ int   c_src_t[8]  = {0, 0, 1, 1, 0, 1, 2, 2};
__constant__ int   c_dst_t[8]  = {1, 2, 2, 1, 0, 0, 1, 0};
__constant__ int   c_woff[8]   = {0, 50, 2050, 4050, 4100, 24100, 44100, 44150};
__constant__ int   c_t2e[3][3] = {{4, 5, 7}, {0, 3, 6}, {1, 2, -1}};
__constant__ float c_invcnt[3] = {1.0f / 3.0f, 1.0f / 3.0f, 0.5f};

// ---------------------------------------------------------------------------
// K0: zero accumulators + counters; build transposed msg copy.
// ---------------------------------------------------------------------------
__global__ void zero_kernel(const float* __restrict__ msg)
{
    int i = blockIdx.x * 256 + threadIdx.x;
    int stride = gridDim.x * 256;
    float4 z = {0.f, 0.f, 0.f, 0.f};
    float4* w4 = reinterpret_cast<float4*>(g_w);
    float4* d4 = reinterpret_cast<float4*>(g_den);
    for (int k = i; k < WTOT * 32; k += stride) w4[k] = z;
    for (int k = i; k < WTOT * 2;  k += stride) d4[k] = z;
    for (int k = i; k < WTOT;      k += stride) g_cnt[k] = 0;
    for (int k = i; k < 16384;     k += stride) {
        int f  = k & 15;
        int dd = (k >> 4) & 15;
        int h  = (k >> 8) & 7;
        int e  = k >> 11;
        g_msgT[e * 2048 + dd * 128 + h * 16 + f] = msg[k];
    }
}

// ---------------------------------------------------------------------------
// K1: histogram of edges per (etype,dst) slot
// ---------------------------------------------------------------------------
__global__ void hist_kernel(const int* __restrict__ edst)
{
    int idx = blockIdx.x * 256 + threadIdx.x;
    if (idx >= E_TOT) return;
    int e = idx / E_PER;
    atomicAdd(&g_cnt[c_woff[e] + edst[idx]], 1);
}

// ---------------------------------------------------------------------------
// K2: exclusive scan of g_cnt -> g_pos (scatter cursors). Single block.
// ---------------------------------------------------------------------------
__global__ void __launch_bounds__(1024) scan_kernel()
{
    __shared__ int ss[1024];
    int t = threadIdx.x;
    int base = t * 63;
    int s = 0;
    for (int j = 0; j < 63; j++) {
        int idx = base + j;
        if (idx < WTOT) s += g_cnt[idx];
    }
    ss[t] = s;
    __syncthreads();
    for (int off = 1; off < 1024; off <<= 1) {
        int v = (t >= off) ? ss[t - off] : 0;
        __syncthreads();
        ss[t] += v;
        __syncthreads();
    }
    int run = ss[t] - s;   // exclusive prefix of this thread's chunk
    for (int j = 0; j < 63; j++) {
        int idx = base + j;
        if (idx < WTOT) {
            g_pos[idx] = run;
            run += g_cnt[idx];
        }
    }
}

// ---------------------------------------------------------------------------
// K3: scatter edges into dst-sorted order. rec = (slot<<15) | src_global.
// slot < 64150 (17 bits), src_global < 22050 (15 bits).
// ---------------------------------------------------------------------------
__global__ void scatter_kernel(const int* __restrict__ esrc,
                               const int* __restrict__ edst)
{
    int idx = blockIdx.x * 256 + threadIdx.x;
    if (idx >= E_TOT) return;
    int e = idx / E_PER;
    unsigned slot = (unsigned)(c_woff[e] + edst[idx]);
    unsigned sg   = (unsigned)(c_off[c_src_t[e]] + esrc[idx]);
    int pos = atomicAdd(&g_pos[slot], 1);
    g_rec[pos] = (slot << 15) | sg;
}

// ---------------------------------------------------------------------------
// K4: projections (unchanged). block = 128 threads, 32 nodes per block.
// ---------------------------------------------------------------------------
__global__ void __launch_bounds__(128) proj_kernel(
    const float* __restrict__ xw, const float* __restrict__ xt,
    const float* __restrict__ xd,
    const float* __restrict__ Wk, const float* __restrict__ bk,
    const float* __restrict__ Wq, const float* __restrict__ bq,
    const float* __restrict__ Wv, const float* __restrict__ bv)
{
    int t  = blockIdx.z;
    int Nt = c_nt[t];
    int n0 = blockIdx.x * 32;
    if (n0 >= Nt) return;

    const float* x = (t == 0) ? xw : (t == 1) ? xt : xd;
    int m = blockIdx.y;
    const float* W = ((m == 0) ? Wk : (m == 1) ? Wq : Wv) + t * 256 * 128;
    const float* b = ((m == 0) ? bk : (m == 1) ? bq : bv) + t * 128;
    float* out = ((m == 0) ? g_k : (m == 1) ? g_q : g_v) + (size_t)(c_off[t] + n0) * 128;

    int j = threadIdx.x;

    unsigned long long acc2[16];
#pragma unroll
    for (int p = 0; p < 16; p++) acc2[p] = 0ull;

    __shared__ float xs[16][32];

    for (int kk = 0; kk < 256; kk += 16) {
        __syncthreads();
#pragma unroll
        for (int p = 0; p < 4; p++) {
            int idx = j + p * 128;
            int kc = idx >> 5, i = idx & 31;
            int n = n0 + i;
            xs[kc][i] = (n < Nt) ? x[(size_t)n * 256 + kk + kc] : 0.0f;
        }
        __syncthreads();
#pragma unroll
        for (int kc = 0; kc < 16; kc++) {
            float wv = W[(size_t)(kk + kc) * 128 + j];
            unsigned long long w2;
            asm("mov.b64 %0, {%1,%1};" : "=l"(w2) : "f"(wv));
#pragma unroll
            for (int p = 0; p < 16; p++) {
                unsigned long long xv =
                    *reinterpret_cast<const unsigned long long*>(&xs[kc][2 * p]);
                asm("fma.rn.f32x2 %0, %1, %2, %3;"
                    : "=l"(acc2[p]) : "l"(xv), "l"(w2), "l"(acc2[p]));
            }
        }
    }

    float bb = b[j];
#pragma unroll
    for (int p = 0; p < 16; p++) {
        float lo, hi;
        asm("mov.b64 {%0,%1}, %2;" : "=f"(lo), "=f"(hi) : "l"(acc2[p]));
        int n = n0 + 2 * p;
        if (n < Nt)     out[(size_t)(2 * p) * 128 + j]     = lo + bb;
        if (n + 1 < Nt) out[(size_t)(2 * p + 1) * 128 + j] = hi + bb;
    }
}

// ---------------------------------------------------------------------------
// K5: accumulation over the sorted edge stream. One warp per 64-edge chunk.
// Runs (consecutive edges with same slot) accumulate in registers; one
// red.v4 flush per run. lane l owns dims [4l,4l+4), head h = l>>2.
// ---------------------------------------------------------------------------
__global__ void __launch_bounds__(256) accum_kernel(const float* __restrict__ pri)
{
    int w = blockIdx.x * 8 + (threadIdx.x >> 5);
    if (w >= NCHUNK) return;
    int l = threadIdx.x & 31;
    int h = l >> 2;
    int i = w * CH;
    const int i1 = i + CH;
    unsigned rec = g_rec[i];

    for (;;) {
        unsigned slot = rec >> 15;
        int e = (slot >= 44150u) ? 7 : (slot >= 44100u) ? 6 : (slot >= 24100u) ? 5 :
                (slot >= 4100u)  ? 4 : (slot >= 4050u)  ? 3 : (slot >= 2050u)  ? 2 :
                (slot >= 50u)    ? 1 : 0;
        int dg = c_off[c_dst_t[e]] + (int)slot - c_woff[e];
        float4 q4 = *reinterpret_cast<const float4*>(g_q + (size_t)dg * 128 + 4 * l);
        float pr = pri[e * 8 + h] * 0.25f;

        float4 acc = make_float4(0.f, 0.f, 0.f, 0.f);
        float den = 0.f;
        bool last = false;

        for (;;) {
            unsigned sg = rec & 0x7FFFu;
            float4 k4 = *reinterpret_cast<const float4*>(g_k + (size_t)sg * 128 + 4 * l);
            float4 v4 = *reinterpret_cast<const float4*>(g_v + (size_t)sg * 128 + 4 * l);
            ++i;
            unsigned nrec = 0u;
            if (i < i1) nrec = g_rec[i];

            float p = q4.x * k4.x + q4.y * k4.y + q4.z * k4.z + q4.w * k4.w;
            p += __shfl_xor_sync(0xffffffffu, p, 1);
            p += __shfl_xor_sync(0xffffffffu, p, 2);
            float ex = __expf(p * pr);

            acc.x += ex * v4.x; acc.y += ex * v4.y;
            acc.z += ex * v4.z; acc.w += ex * v4.w;
            den += ex;

            if (i >= i1) { last = true; break; }
            rec = nrec;
            if ((rec >> 15) != slot) break;
        }

        float* wp = g_w + (size_t)slot * 128 + 4 * l;
        asm volatile("red.global.add.v4.f32 [%0], {%1,%2,%3,%4};"
                     :: "l"(wp), "f"(acc.x), "f"(acc.y), "f"(acc.z), "f"(acc.w)
                     : "memory");
        if ((l & 3) == 0)
            atomicAdd(&g_den[(size_t)slot * 8 + h], den);

        if (last) break;
    }
}

// ---------------------------------------------------------------------------
// K6: node epilogue. warp per node; lane l owns output cols [4l,4l+4).
// w row loaded as one coalesced float4/lane, w[dd] distributed via shfl;
// msg read from transposed copy -> fully coalesced float4 per dd.
// ---------------------------------------------------------------------------
__global__ void __launch_bounds__(256) out_kernel(
    const float* __restrict__ gamma, const float* __restrict__ beta,
    float* __restrict__ out)
{
    int n = blockIdx.x * 8 + (threadIdx.x >> 5);
    if (n >= NNODE) return;
    int l = threadIdx.x & 31;
    int h = l >> 2;
    int t = (n < 20000) ? 0 : (n < 20050) ? 1 : 2;
    int local = n - c_off[t];

    float4 acc = make_float4(0.f, 0.f, 0.f, 0.f);
#pragma unroll
    for (int ee = 0; ee < 3; ee++) {
        int e = c_t2e[t][ee];
        if (e >= 0) {   // warp-uniform (same node across warp)
            unsigned slot = (unsigned)(c_woff[e] + local);
            float den = g_den[(size_t)slot * 8 + h];
            float inv = (den > 0.f) ? (1.0f / den) : 0.f;  // branch-free, g_w zeroed
            float4 w4 = *reinterpret_cast<const float4*>(g_w + (size_t)slot * 128 + 4 * l);
            const float* mb = g_msgT + e * 2048 + h * 16 + (l & 3) * 4;
            float4 ea = make_float4(0.f, 0.f, 0.f, 0.f);
#pragma unroll
            for (int dd = 0; dd < 16; dd++) {
                float wc = ((dd & 3) == 0) ? w4.x : ((dd & 3) == 1) ? w4.y :
                           ((dd & 3) == 2) ? w4.z : w4.w;
                float wd = __shfl_sync(0xffffffffu, wc, (l & ~3) | (dd >> 2));
                float4 m4 = *reinterpret_cast<const float4*>(mb + dd * 128);
                ea.x += wd * m4.x; ea.y += wd * m4.y;
                ea.z += wd * m4.z; ea.w += wd * m4.w;
            }
            acc.x += inv * ea.x; acc.y += inv * ea.y;
            acc.z += inv * ea.z; acc.w += inv * ea.w;
        }
    }

    float ic = c_invcnt[t];
    float hv[4], s = 0.f, s2 = 0.f;
    float av[4] = {acc.x, acc.y, acc.z, acc.w};
#pragma unroll
    for (int j = 0; j < 4; j++) {
        float v = fmaxf(av[j] * ic, 0.f);
        hv[j] = v;
        s += v;
        s2 += v * v;
    }
#pragma unroll
    for (int o = 16; o >= 1; o >>= 1) {
        s  += __shfl_xor_sync(0xffffffffu, s,  o);
        s2 += __shfl_xor_sync(0xffffffffu, s2, o);
    }
    float mu   = s * (1.0f / 128.0f);
    float var  = s2 * (1.0f / 128.0f) - mu * mu;
    float rstd = rsqrtf(var + 1e-5f);
#pragma unroll
    for (int j = 0; j < 4; j++) {
        int col = 4 * l + j;
        out[(size_t)n * 128 + col] =
            (hv[j] - mu) * rstd * gamma[t * 128 + col] + beta[t * 128 + col];
    }
}

// ---------------------------------------------------------------------------
extern "C" void kernel_launch(void* const* d_in, const int* in_sizes, int n_in,
                              void* d_out, int out_size)
{
    const float* xw    = (const float*)d_in[0];
    const float* xt    = (const float*)d_in[1];
    const float* xd    = (const float*)d_in[2];
    const float* Wk    = (const float*)d_in[3];
    const float* bk    = (const float*)d_in[4];
    const float* Wq    = (const float*)d_in[5];
    const float* bq    = (const float*)d_in[6];
    const float* Wv    = (const float*)d_in[7];
    const float* bv    = (const float*)d_in[8];
    const float* pri   = (const float*)d_in[9];
    const float* msg   = (const float*)d_in[10];
    const float* gamma = (const float*)d_in[11];
    const float* beta  = (const float*)d_in[12];
    const int*   esrc  = (const int*)d_in[13];
    const int*   edst  = (const int*)d_in[14];
    float* out = (float*)d_out;

    int eblocks = (E_TOT + 255) / 256;

    zero_kernel<<<2048, 256>>>(msg);
    hist_kernel<<<eblocks, 256>>>(edst);
    scan_kernel<<<1, 1024>>>();
    scatter_kernel<<<eblocks, 256>>>(esrc, edst);
    dim3 gp(625, 3, 3);
    proj_kernel<<<gp, 128>>>(xw, xt, xd, Wk, bk, Wq, bq, Wv, bv);
    accum_kernel<<<(NCHUNK + 7) / 8, 256>>>(pri);
    out_kernel<<<(NNODE + 7) / 8, 256>>>(gamma, beta, out);
}